// round 8
// baseline (speedup 1.0000x reference)
#include <cuda_runtime.h>

#define DNUM 20
#define ONUM 19
#define MNUM 32
#define MM   1024
#define NAB  (ONUM * ONUM)                // 361
#define NROWS (ONUM * ONUM * ONUM)        // 6859
#define ROWF  (DNUM * MNUM)               // 640

typedef unsigned long long u64;

// transposed tables: CT[k][j][i] = cos(2*pi*k/(32*i+j+2)), PT[j][i] = P[i][j]
__device__ __align__(16) float g_CT[ONUM * MM];
__device__ __align__(16) float g_PT[MM];
__device__ __align__(16) float g_G[NAB * MM];      // G[ab][j][i] = PT * CTa * CTb
__device__ __align__(16) float g_XT[NROWS * ROWF]; // [row][j][d(20, last=0)]

__device__ __forceinline__ u64 ffma2(u64 a, u64 b, u64 c) {
    u64 d;
    asm("fma.rn.f32x2 %0, %1, %2, %3;" : "=l"(d) : "l"(a), "l"(b), "l"(c));
    return d;
}
__device__ __forceinline__ u64 pk2(float lo, float hi) {
    u64 r;
    asm("mov.b64 %0, {%1, %2};" : "=l"(r) : "f"(lo), "f"(hi));
    return r;
}
__device__ __forceinline__ void upk2(u64 v, float& lo, float& hi) {
    asm("mov.b64 {%0, %1}, %2;" : "=f"(lo), "=f"(hi) : "l"(v));
}

__global__ void init_tabs(const float* __restrict__ P) {
    int t = blockIdx.x * blockDim.x + threadIdx.x;
    if (t < ONUM * MM) {
        int k = t / MM, r = t % MM;
        int j = r >> 5, i = r & 31;
        g_CT[t] = cosf(6.283185307179586f * (float)k / (float)(i * MNUM + j + 2));
    } else if (t < ONUM * MM + MM) {
        int e = t - ONUM * MM;                    // e = j*32 + i
        g_PT[e] = P[(e & 31) * MNUM + (e >> 5)];
    }
}

__global__ __launch_bounds__(256) void k_gab() {
    const int ab = blockIdx.x;
    const int a = ab / ONUM, b = ab % ONUM;
    const int e = threadIdx.x;
    float4 p  = ((const float4*)g_PT)[e];
    float4 av = ((const float4*)(g_CT + a * MM))[e];
    float4 bv = ((const float4*)(g_CT + b * MM))[e];
    float4 o;
    o.x = p.x * av.x * bv.x;
    o.y = p.y * av.y * bv.y;
    o.z = p.z * av.z * bv.z;
    o.w = p.w * av.w * bv.w;
    ((float4*)(g_G + ab * MM))[e] = o;
}

// k12b: one block per (a,b). H2 -> matvec -> window(c,d) -> XT rows for c=0..18.
#define K12_THREADS 512
#define H2F 12800                          // 20*20*32
#define X2STR 33                           // padded j stride
#define X2F (DNUM * DNUM * X2STR)          // 13200
#define K12_SMEM ((H2F + X2F) * 4)

__global__ __launch_bounds__(K12_THREADS) void k12b(const float* __restrict__ h,
                                                    const float* __restrict__ Mw) {
    extern __shared__ __align__(16) float dsm[];
    float* sH2 = dsm;                      // [c'][d'][k]  20*20*32
    float* sX2 = dsm + H2F;                // [c'][d'][j]  stride 33

    const int tid = threadIdx.x;
    const int ab = blockIdx.x;
    const int a = ab / ONUM, b = ab % ONUM;
    const int w = tid >> 5, lane = tid & 31;

    // phase A: H2 = sum over {da,db} of h[a+da,b+db,:,:,:], contiguous f4 streams
    // h plane base for (a,b): (a*DNUM + b) * 3200 float4; db:+3200, da:+64000
    {
        const float4* p00 = (const float4*)h + (a * DNUM + b) * 3200;
        float4* o4 = (float4*)sH2;
#pragma unroll
        for (int e = tid; e < 3200; e += K12_THREADS) {
            float4 r0 = __ldg(p00 + e);
            float4 r1 = __ldg(p00 + e + 3200);
            float4 r2 = __ldg(p00 + e + 64000);
            float4 r3 = __ldg(p00 + e + 67200);
            float4 o;
            o.x = (r0.x + r1.x) + (r2.x + r3.x);
            o.y = (r0.y + r1.y) + (r2.y + r3.y);
            o.z = (r0.z + r1.z) + (r2.z + r3.z);
            o.w = (r0.w + r1.w) + (r2.w + r3.w);
            o4[e] = o;
        }
    }
    __syncthreads();

    // phase B: X2[c',d',j] = sum_k M[j,k] * H2[c',d',k]; lane = j, warp per point
    {
        float Mr[MNUM];
        const float4* M4 = (const float4*)Mw + lane * 8;
#pragma unroll
        for (int v = 0; v < 8; ++v) {
            float4 m = __ldg(M4 + v);
            Mr[4*v+0] = m.x; Mr[4*v+1] = m.y; Mr[4*v+2] = m.z; Mr[4*v+3] = m.w;
        }
#pragma unroll
        for (int pt = w; pt < DNUM * DNUM; pt += K12_THREADS / 32) {
            const float4* H4 = (const float4*)sH2 + pt * 8;
            float a0 = 0.f, a1 = 0.f, a2 = 0.f, a3 = 0.f;
#pragma unroll
            for (int v = 0; v < 8; ++v) {
                float4 hv = H4[v];                 // uniform LDS broadcast
                a0 = fmaf(Mr[4*v+0], hv.x, a0);
                a1 = fmaf(Mr[4*v+1], hv.y, a1);
                a2 = fmaf(Mr[4*v+2], hv.z, a2);
                a3 = fmaf(Mr[4*v+3], hv.w, a3);
            }
            sX2[pt * X2STR + lane] = (a0 + a1) + (a2 + a3);
        }
    }
    __syncthreads();

    // phase C: window over (c,d), transpose to [j][d(20)], write 19 XT rows
#pragma unroll
    for (int idx = tid; idx < ONUM * 160; idx += K12_THREADS) {
        const int c = idx / 160, e = idx - c * 160;
        const int f0 = e * 4;
        const int j0 = f0 / 20, d0 = f0 - (f0 / 20) * 20;  // 20%4==0: one j per f4
        const float* b0 = sX2 + (c * DNUM + d0) * X2STR + j0;
        const float* b1 = b0 + DNUM * X2STR;
        float q[4];
#pragma unroll
        for (int t = 0; t < 4; ++t) {
            const int d = d0 + t;
            q[t] = (d < ONUM)
                 ? ((b0[t * X2STR] + b0[(t + 1) * X2STR])
                  + (b1[t * X2STR] + b1[(t + 1) * X2STR])) * 0.0625f
                 : 0.0f;
        }
        float4 v; v.x = q[0]; v.y = q[1]; v.z = q[2]; v.w = q[3];
        ((float4*)(g_XT + (ab * ONUM + c) * ROWF))[e] = v;
    }
}

// main: warp per row, lane = i; j outer, packed Chebyshev double-step inner
#define WPB 4
__global__ __launch_bounds__(WPB * 32, 6)
void sdd_main(float* __restrict__ out) {
    __shared__ __align__(16) float sX[WPB][ROWF];

    const int w = threadIdx.x >> 5, lane = threadIdx.x & 31;
    const int row = blockIdx.x * WPB + w;
    if (row >= NROWS) return;

    const int a = row / NAB;
    const int bc = row - a * NAB;
    const int b = bc / ONUM;
    const int c = bc - b * ONUM;
    const int ab = a * ONUM + b;

    {
        const float4* xr4 = (const float4*)(g_XT + row * ROWF);
        float4* s4 = (float4*)sX[w];
#pragma unroll
        for (int q = 0; q < 5; ++q)
            s4[lane + 32 * q] = __ldg(xr4 + lane + 32 * q);
    }
    __syncwarp();

    const float* Gp = g_G + ab * MM + lane;
    const float* Cc = g_CT + c * MM + lane;
    const float* C1 = g_CT + MM + lane;
    const ulonglong2* xs = (const ulonglong2*)sX[w];

    u64 acc[10];
#pragma unroll
    for (int k = 0; k < 10; ++k) acc[k] = 0ull;

#pragma unroll 2
    for (int j = 0; j < MNUM; ++j) {
        const float tc = 2.0f * __ldg(C1 + j * MNUM);
        const float u0 = __ldg(Gp + j * MNUM) * __ldg(Cc + j * MNUM);
        const float csq = tc * tc;
        const u64 tc2  = pk2(csq - 2.0f, csq - 2.0f);
        const u64 ntc2 = pk2(2.0f - csq, 2.0f - csq);
        const float t1 = 0.5f * tc * u0;
        const float t2 = fmaf(tc, t1, -u0);
        const float t3 = fmaf(tc, t2, -t1);

        ulonglong2 xa = xs[j * 5 + 0];
        ulonglong2 xb = xs[j * 5 + 1];
        ulonglong2 xc = xs[j * 5 + 2];
        ulonglong2 xd = xs[j * 5 + 3];
        ulonglong2 xe = xs[j * 5 + 4];

        u64 s0 = pk2(u0, t1);
        u64 s1 = pk2(t2, t3);
        acc[0] = ffma2(xa.x, s0, acc[0]);
        acc[1] = ffma2(xa.y, s1, acc[1]);
        u64 s2 = ffma2(ntc2, s1, s0);
        acc[2] = ffma2(xb.x, s2, acc[2]);
        u64 s3 = ffma2(tc2, s2, s1);
        acc[3] = ffma2(xb.y, s3, acc[3]);
        s0 = ffma2(ntc2, s3, s2);
        acc[4] = ffma2(xc.x, s0, acc[4]);
        s1 = ffma2(tc2, s0, s3);
        acc[5] = ffma2(xc.y, s1, acc[5]);
        s2 = ffma2(ntc2, s1, s0);
        acc[6] = ffma2(xd.x, s2, acc[6]);
        s3 = ffma2(tc2, s2, s1);
        acc[7] = ffma2(xd.y, s3, acc[7]);
        s0 = ffma2(ntc2, s3, s2);
        acc[8] = ffma2(xe.x, s0, acc[8]);
        s1 = ffma2(tc2, s0, s3);
        acc[9] = ffma2(xe.y, s1, acc[9]);
    }

    float* op = out + row * (ONUM * MNUM) + lane;
#pragma unroll
    for (int k = 0; k < 10; ++k) {
        float lo, hi;
        upk2(acc[k], lo, hi);
        const float s = (k & 2) ? -1.0f : 1.0f;
        op[(2 * k) * MNUM] = s * lo;
        if (2 * k + 1 < ONUM) op[(2 * k + 1) * MNUM] = s * hi;
    }
}

extern "C" void kernel_launch(void* const* d_in, const int* in_sizes, int n_in,
                              void* d_out, int out_size) {
    const float* h  = (const float*)d_in[0];   // hypervol [20,20,20,20,32]
    const float* Mw = (const float*)d_in[1];   // M_w [32,32]
    const float* P  = (const float*)d_in[2];   // P  [32,32]
    float* out = (float*)d_out;                // [130321, 32]

    static int smem_set = 0;
    if (!smem_set) {
        cudaFuncSetAttribute(k12b, cudaFuncAttributeMaxDynamicSharedMemorySize,
                             K12_SMEM);
        smem_set = 1;
    }

    init_tabs<<<(ONUM * MM + MM + 511) / 512, 512>>>(P);
    k_gab<<<NAB, 256>>>();
    k12b<<<NAB, K12_THREADS, K12_SMEM>>>(h, Mw);
    sdd_main<<<(NROWS + WPB - 1) / WPB, WPB * 32>>>(out);
}

// round 9
// speedup vs baseline: 1.3803x; 1.3803x over previous
#include <cuda_runtime.h>

#define DNUM 20
#define ONUM 19
#define MNUM 32
#define MM   1024
#define NAB  (ONUM * ONUM)                // 361
#define ROWOUT (ONUM * MNUM)              // 608 floats per (a,b,c) out row

typedef unsigned long long u64;

// transposed tables: CT[k][j][i] = cos(2*pi*k/(32*i+j+2)), PT[j][i] = P[i][j]
__device__ __align__(16) float g_CT[ONUM * MM];
__device__ __align__(16) float g_PT[MM];

__device__ __forceinline__ u64 ffma2(u64 a, u64 b, u64 c) {
    u64 d;
    asm("fma.rn.f32x2 %0, %1, %2, %3;" : "=l"(d) : "l"(a), "l"(b), "l"(c));
    return d;
}
__device__ __forceinline__ u64 pk2(float lo, float hi) {
    u64 r;
    asm("mov.b64 %0, {%1, %2};" : "=l"(r) : "f"(lo), "f"(hi));
    return r;
}
__device__ __forceinline__ void upk2(u64 v, float& lo, float& hi) {
    asm("mov.b64 {%0, %1}, %2;" : "=f"(lo), "=f"(hi) : "l"(v));
}

__global__ void init_tabs(const float* __restrict__ P) {
    int t = blockIdx.x * blockDim.x + threadIdx.x;
    if (t < ONUM * MM) {
        int k = t / MM, r = t % MM;
        int j = r >> 5, i = r & 31;
        g_CT[t] = cosf(6.283185307179586f * (float)k / (float)(i * MNUM + j + 2));
    } else if (t < ONUM * MM + MM) {
        int e = t - ONUM * MM;                    // e = j*32 + i
        g_PT[e] = P[(e & 31) * MNUM + (e >> 5)];
    }
}

// Fully fused: one block per (a,b). H2 -> matvec -> window -> Chebyshev -> out.
#define FT 640                             // 20 warps
#define H2F 12800                          // 20*20*32  (reused as WX: 19*640)
#define X2STR 33
#define X2F (DNUM * DNUM * X2STR)          // 13200
#define F_SMEM ((H2F + X2F) * 4)           // 104000 B

__global__ __launch_bounds__(FT) void fused(const float* __restrict__ h,
                                            const float* __restrict__ Mw,
                                            float* __restrict__ out) {
    extern __shared__ __align__(16) float dsm[];
    float* sH2 = dsm;                      // phase A/B: H2[c'][d'][k]; phase C/D: WX
    float* sX2 = dsm + H2F;                // X2[c'][d'][j], stride 33

    const int tid = threadIdx.x;
    const int ab = blockIdx.x;
    const int a = ab / ONUM, b = ab % ONUM;
    const int w = tid >> 5, lane = tid & 31;

    // phase A: H2 = sum over {da,db} of h[a+da, b+db, :, :, :]
    // plane base (a,b): (a*DNUM+b)*3200 float4; db:+3200, da:+64000
    {
        const float4* p00 = (const float4*)h + (a * DNUM + b) * 3200;
        float4* o4 = (float4*)sH2;
#pragma unroll
        for (int e = tid; e < 3200; e += FT) {
            float4 r0 = __ldg(p00 + e);
            float4 r1 = __ldg(p00 + e + 3200);
            float4 r2 = __ldg(p00 + e + 64000);
            float4 r3 = __ldg(p00 + e + 67200);
            float4 o;
            o.x = (r0.x + r1.x) + (r2.x + r3.x);
            o.y = (r0.y + r1.y) + (r2.y + r3.y);
            o.z = (r0.z + r1.z) + (r2.z + r3.z);
            o.w = (r0.w + r1.w) + (r2.w + r3.w);
            o4[e] = o;
        }
    }
    __syncthreads();

    // phase B: X2[c',d',j] = sum_k M[j,k] * H2[c',d',k]; lane = j, warp per point
    {
        float Mr[MNUM];
        const float4* M4 = (const float4*)Mw + lane * 8;
#pragma unroll
        for (int v = 0; v < 8; ++v) {
            float4 m = __ldg(M4 + v);
            Mr[4*v+0] = m.x; Mr[4*v+1] = m.y; Mr[4*v+2] = m.z; Mr[4*v+3] = m.w;
        }
#pragma unroll
        for (int pt = w; pt < DNUM * DNUM; pt += FT / 32) {
            const float4* H4 = (const float4*)sH2 + pt * 8;
            float a0 = 0.f, a1 = 0.f, a2 = 0.f, a3 = 0.f;
#pragma unroll
            for (int v = 0; v < 8; ++v) {
                float4 hv = H4[v];                 // uniform LDS broadcast
                a0 = fmaf(Mr[4*v+0], hv.x, a0);
                a1 = fmaf(Mr[4*v+1], hv.y, a1);
                a2 = fmaf(Mr[4*v+2], hv.z, a2);
                a3 = fmaf(Mr[4*v+3], hv.w, a3);
            }
            sX2[pt * X2STR + lane] = (a0 + a1) + (a2 + a3);
        }
    }
    __syncthreads();

    // phase C: window over (c,d), transpose -> WX[c][j][d(20, last=0)] over sH2
#pragma unroll
    for (int idx = tid; idx < ONUM * 160; idx += FT) {
        const int c = idx / 160, e = idx - c * 160;
        const int f0 = e * 4;
        const int j0 = f0 / 20, d0 = f0 - (f0 / 20) * 20;  // 20%4==0
        const float* b0 = sX2 + (c * DNUM + d0) * X2STR + j0;
        const float* b1 = b0 + DNUM * X2STR;
        float q[4];
#pragma unroll
        for (int t = 0; t < 4; ++t) {
            const int d = d0 + t;
            q[t] = (d < ONUM)
                 ? ((b0[t * X2STR] + b0[(t + 1) * X2STR])
                  + (b1[t * X2STR] + b1[(t + 1) * X2STR])) * 0.0625f
                 : 0.0f;
        }
        float4 v; v.x = q[0]; v.y = q[1]; v.z = q[2]; v.w = q[3];
        ((float4*)(sH2 + c * 640))[e] = v;
    }
    __syncthreads();

    // phase D: warp w = row c (<19); lane = i; packed Chebyshev double-step
    if (w < ONUM) {
        const int c = w;
        const float* PTl = g_PT + lane;
        const float* Ca  = g_CT + a * MM + lane;
        const float* Cb  = g_CT + b * MM + lane;
        const float* Cc  = g_CT + c * MM + lane;
        const float* C1  = g_CT + MM + lane;
        const ulonglong2* xs = (const ulonglong2*)(sH2 + c * 640);

        u64 acc[10];
#pragma unroll
        for (int k = 0; k < 10; ++k) acc[k] = 0ull;

#pragma unroll 2
        for (int j = 0; j < MNUM; ++j) {
            const int o = j * MNUM;
            const float tc = 2.0f * __ldg(C1 + o);
            const float u0 = __ldg(PTl + o) * __ldg(Ca + o)
                           * __ldg(Cb + o) * __ldg(Cc + o);
            const float csq = tc * tc;
            const u64 tc2  = pk2(csq - 2.0f, csq - 2.0f);
            const u64 ntc2 = pk2(2.0f - csq, 2.0f - csq);
            const float t1 = 0.5f * tc * u0;
            const float t2 = fmaf(tc, t1, -u0);
            const float t3 = fmaf(tc, t2, -t1);

            ulonglong2 xa = xs[j * 5 + 0];
            ulonglong2 xb = xs[j * 5 + 1];
            ulonglong2 xc = xs[j * 5 + 2];
            ulonglong2 xd = xs[j * 5 + 3];
            ulonglong2 xe = xs[j * 5 + 4];

            u64 s0 = pk2(u0, t1);
            u64 s1 = pk2(t2, t3);
            acc[0] = ffma2(xa.x, s0, acc[0]);
            acc[1] = ffma2(xa.y, s1, acc[1]);
            u64 s2 = ffma2(ntc2, s1, s0);
            acc[2] = ffma2(xb.x, s2, acc[2]);
            u64 s3 = ffma2(tc2, s2, s1);
            acc[3] = ffma2(xb.y, s3, acc[3]);
            s0 = ffma2(ntc2, s3, s2);
            acc[4] = ffma2(xc.x, s0, acc[4]);
            s1 = ffma2(tc2, s0, s3);
            acc[5] = ffma2(xc.y, s1, acc[5]);
            s2 = ffma2(ntc2, s1, s0);
            acc[6] = ffma2(xd.x, s2, acc[6]);
            s3 = ffma2(tc2, s2, s1);
            acc[7] = ffma2(xd.y, s3, acc[7]);
            s0 = ffma2(ntc2, s3, s2);
            acc[8] = ffma2(xe.x, s0, acc[8]);
            s1 = ffma2(tc2, s0, s3);
            acc[9] = ffma2(xe.y, s1, acc[9]);
        }

        float* op = out + (ab * ONUM + c) * ROWOUT + lane;
#pragma unroll
        for (int k = 0; k < 10; ++k) {
            float lo, hi;
            upk2(acc[k], lo, hi);
            const float s = (k & 2) ? -1.0f : 1.0f;
            op[(2 * k) * MNUM] = s * lo;
            if (2 * k + 1 < ONUM) op[(2 * k + 1) * MNUM] = s * hi;
        }
    }
}

extern "C" void kernel_launch(void* const* d_in, const int* in_sizes, int n_in,
                              void* d_out, int out_size) {
    const float* h  = (const float*)d_in[0];   // hypervol [20,20,20,20,32]
    const float* Mw = (const float*)d_in[1];   // M_w [32,32]
    const float* P  = (const float*)d_in[2];   // P  [32,32]
    float* out = (float*)d_out;                // [130321, 32]

    static int smem_set = 0;
    if (!smem_set) {
        cudaFuncSetAttribute(fused, cudaFuncAttributeMaxDynamicSharedMemorySize,
                             F_SMEM);
        smem_set = 1;
    }

    init_tabs<<<(ONUM * MM + MM + 511) / 512, 512>>>(P);
    fused<<<NAB, FT, F_SMEM>>>(h, Mw, out);
}

// round 10
// speedup vs baseline: 1.4817x; 1.0734x over previous
#include <cuda_runtime.h>

#define DNUM 20
#define ONUM 19
#define MNUM 32
#define MM   1024
#define NAB  (ONUM * ONUM)                // 361
#define ROWOUT (ONUM * MNUM)              // 608

typedef unsigned long long u64;

// transposed tables: CT[k][j][i] = cos(2*pi*k/(32*i+j+2)), PT[j][i] = P[i][j]
__device__ __align__(16) float g_CT[ONUM * MM];
__device__ __align__(16) float g_PT[MM];

__device__ __forceinline__ u64 ffma2(u64 a, u64 b, u64 c) {
    u64 d;
    asm("fma.rn.f32x2 %0, %1, %2, %3;" : "=l"(d) : "l"(a), "l"(b), "l"(c));
    return d;
}
__device__ __forceinline__ u64 pk2(float lo, float hi) {
    u64 r;
    asm("mov.b64 %0, {%1, %2};" : "=l"(r) : "f"(lo), "f"(hi));
    return r;
}
__device__ __forceinline__ void upk2(u64 v, float& lo, float& hi) {
    asm("mov.b64 {%0, %1}, %2;" : "=f"(lo), "=f"(hi) : "l"(v));
}

__global__ void init_tabs(const float* __restrict__ P) {
    int t = blockIdx.x * blockDim.x + threadIdx.x;
    if (t < ONUM * MM) {
        int k = t / MM, r = t % MM;
        int j = r >> 5, i = r & 31;
        g_CT[t] = cosf(6.283185307179586f * (float)k / (float)(i * MNUM + j + 2));
    } else if (t < ONUM * MM + MM) {
        int e = t - ONUM * MM;                    // e = j*32 + i
        g_PT[e] = P[(e & 31) * MNUM + (e >> 5)];
    }
}

// Fused, c-quartered: block = (a,b,cq). 4 blocks/SM for cross-block overlap.
#define FT 256                              // 8 warps
#define CQ 4
#define CRMAX 6                             // max c' rows (5 c-rows + halo)
#define H2F (CRMAX * DNUM * MNUM)           // 3840 floats
#define X2STR 33
#define X2F (CRMAX * DNUM * X2STR)          // 3960
#define F_SMEM ((H2F + X2F) * 4)            // 31200 B

__global__ __launch_bounds__(FT, 4) void fused(const float* __restrict__ h,
                                               const float* __restrict__ Mw,
                                               float* __restrict__ out) {
    __shared__ __align__(16) float sH2[H2F];   // A/B: H2[cl][d'][k]; C/D: WX[lc][j][d20]
    __shared__ __align__(16) float sX2[X2F];   // X2[cl][d'][j], stride 33

    const int tid = threadIdx.x;
    const int blk = blockIdx.x;
    const int ab = blk >> 2, cq = blk & 3;
    const int a = ab / ONUM, b = ab % ONUM;
    const int c0 = cq * 5;
    const int crows = (cq < 3) ? 5 : 4;        // c rows this block outputs
    const int cr = crows + 1;                  // c' rows incl. halo
    const int w = tid >> 5, lane = tid & 31;

    // phase A: H2[cl][d'][k] = sum over {da,db} of h[a+da, b+db, c0+cl, d', k]
    // f4 base: (a*20+b)*3200 + c0*160; db:+3200, da:+64000 (in float4)
    {
        const float4* p00 = (const float4*)h + (a * DNUM + b) * 3200 + c0 * 160;
        float4* o4 = (float4*)sH2;
        const int tot = cr * 160;
        for (int e = tid; e < tot; e += FT) {
            float4 r0 = __ldg(p00 + e);
            float4 r1 = __ldg(p00 + e + 3200);
            float4 r2 = __ldg(p00 + e + 64000);
            float4 r3 = __ldg(p00 + e + 67200);
            float4 o;
            o.x = (r0.x + r1.x) + (r2.x + r3.x);
            o.y = (r0.y + r1.y) + (r2.y + r3.y);
            o.z = (r0.z + r1.z) + (r2.z + r3.z);
            o.w = (r0.w + r1.w) + (r2.w + r3.w);
            o4[e] = o;
        }
    }
    __syncthreads();

    // phase B: X2[cl][d'][j] = sum_k M[j,k] * H2[cl][d'][k]; lane = j, warp per pt
    {
        float Mr[MNUM];
        const float4* M4 = (const float4*)Mw + lane * 8;
#pragma unroll
        for (int v = 0; v < 8; ++v) {
            float4 m = __ldg(M4 + v);
            Mr[4*v+0] = m.x; Mr[4*v+1] = m.y; Mr[4*v+2] = m.z; Mr[4*v+3] = m.w;
        }
        const int npt = cr * DNUM;
        for (int pt = w; pt < npt; pt += FT / 32) {
            const float4* H4 = (const float4*)sH2 + pt * 8;
            float a0 = 0.f, a1 = 0.f, a2 = 0.f, a3 = 0.f;
#pragma unroll
            for (int v = 0; v < 8; ++v) {
                float4 hv = H4[v];                 // uniform LDS broadcast
                a0 = fmaf(Mr[4*v+0], hv.x, a0);
                a1 = fmaf(Mr[4*v+1], hv.y, a1);
                a2 = fmaf(Mr[4*v+2], hv.z, a2);
                a3 = fmaf(Mr[4*v+3], hv.w, a3);
            }
            sX2[pt * X2STR + lane] = (a0 + a1) + (a2 + a3);
        }
    }
    __syncthreads();

    // phase C: window over (c,d), transpose -> WX[lc][j][d(20, last=0)] over sH2
    {
        const int tot = crows * 160;
        for (int idx = tid; idx < tot; idx += FT) {
            const int lc = idx / 160, e = idx - lc * 160;
            const int f0 = e * 4;
            const int j0 = f0 / 20, d0 = f0 - (f0 / 20) * 20;  // 20%4==0
            const float* b0 = sX2 + (lc * DNUM + d0) * X2STR + j0;
            const float* b1 = b0 + DNUM * X2STR;
            float q[4];
#pragma unroll
            for (int t = 0; t < 4; ++t) {
                const int d = d0 + t;
                q[t] = (d < ONUM)
                     ? ((b0[t * X2STR] + b0[(t + 1) * X2STR])
                      + (b1[t * X2STR] + b1[(t + 1) * X2STR])) * 0.0625f
                     : 0.0f;
            }
            float4 v; v.x = q[0]; v.y = q[1]; v.z = q[2]; v.w = q[3];
            ((float4*)(sH2 + lc * 640))[e] = v;
        }
    }
    __syncthreads();

    // phase D: warp w = local row lc (< crows); lane = i; packed Chebyshev
    if (w < crows) {
        const int c = c0 + w;
        const float* PTl = g_PT + lane;
        const float* Ca  = g_CT + a * MM + lane;
        const float* Cb  = g_CT + b * MM + lane;
        const float* Cc  = g_CT + c * MM + lane;
        const float* C1  = g_CT + MM + lane;
        const ulonglong2* xs = (const ulonglong2*)(sH2 + w * 640);

        u64 acc[10];
#pragma unroll
        for (int k = 0; k < 10; ++k) acc[k] = 0ull;

#pragma unroll 2
        for (int j = 0; j < MNUM; ++j) {
            const int o = j * MNUM;
            const float tc = 2.0f * __ldg(C1 + o);
            const float u0 = __ldg(PTl + o) * __ldg(Ca + o)
                           * __ldg(Cb + o) * __ldg(Cc + o);
            const float csq = tc * tc;
            const u64 tc2  = pk2(csq - 2.0f, csq - 2.0f);
            const u64 ntc2 = pk2(2.0f - csq, 2.0f - csq);
            const float t1 = 0.5f * tc * u0;
            const float t2 = fmaf(tc, t1, -u0);
            const float t3 = fmaf(tc, t2, -t1);

            ulonglong2 xa = xs[j * 5 + 0];
            ulonglong2 xb = xs[j * 5 + 1];
            ulonglong2 xc = xs[j * 5 + 2];
            ulonglong2 xd = xs[j * 5 + 3];
            ulonglong2 xe = xs[j * 5 + 4];

            u64 s0 = pk2(u0, t1);
            u64 s1 = pk2(t2, t3);
            acc[0] = ffma2(xa.x, s0, acc[0]);
            acc[1] = ffma2(xa.y, s1, acc[1]);
            u64 s2 = ffma2(ntc2, s1, s0);
            acc[2] = ffma2(xb.x, s2, acc[2]);
            u64 s3 = ffma2(tc2, s2, s1);
            acc[3] = ffma2(xb.y, s3, acc[3]);
            s0 = ffma2(ntc2, s3, s2);
            acc[4] = ffma2(xc.x, s0, acc[4]);
            s1 = ffma2(tc2, s0, s3);
            acc[5] = ffma2(xc.y, s1, acc[5]);
            s2 = ffma2(ntc2, s1, s0);
            acc[6] = ffma2(xd.x, s2, acc[6]);
            s3 = ffma2(tc2, s2, s1);
            acc[7] = ffma2(xd.y, s3, acc[7]);
            s0 = ffma2(ntc2, s3, s2);
            acc[8] = ffma2(xe.x, s0, acc[8]);
            s1 = ffma2(tc2, s0, s3);
            acc[9] = ffma2(xe.y, s1, acc[9]);
        }

        float* op = out + (ab * ONUM + c) * ROWOUT + lane;
#pragma unroll
        for (int k = 0; k < 10; ++k) {
            float lo, hi;
            upk2(acc[k], lo, hi);
            const float s = (k & 2) ? -1.0f : 1.0f;
            op[(2 * k) * MNUM] = s * lo;
            if (2 * k + 1 < ONUM) op[(2 * k + 1) * MNUM] = s * hi;
        }
    }
}

extern "C" void kernel_launch(void* const* d_in, const int* in_sizes, int n_in,
                              void* d_out, int out_size) {
    const float* h  = (const float*)d_in[0];   // hypervol [20,20,20,20,32]
    const float* Mw = (const float*)d_in[1];   // M_w [32,32]
    const float* P  = (const float*)d_in[2];   // P  [32,32]
    float* out = (float*)d_out;                // [130321, 32]

    init_tabs<<<(ONUM * MM + MM + 511) / 512, 512>>>(P);
    fused<<<NAB * CQ, FT>>>(h, Mw, out);
}

// round 12
// speedup vs baseline: 1.5990x; 1.0792x over previous
#include <cuda_runtime.h>

#define DNUM 20
#define ONUM 19
#define MNUM 32
#define MM   1024
#define NAB  (ONUM * ONUM)                // 361
#define ROWOUT (ONUM * MNUM)              // 608

typedef unsigned long long u64;

// transposed tables: CT[k][j][i] = cos(2*pi*k/(32*i+j+2)), PT[j][i] = P[i][j]
__device__ __align__(16) float g_CT[ONUM * MM];
__device__ __align__(16) float g_PT[MM];

__device__ __forceinline__ u64 ffma2(u64 a, u64 b, u64 c) {
    u64 d;
    asm("fma.rn.f32x2 %0, %1, %2, %3;" : "=l"(d) : "l"(a), "l"(b), "l"(c));
    return d;
}
__device__ __forceinline__ u64 pk2(float lo, float hi) {
    u64 r;
    asm("mov.b64 %0, {%1, %2};" : "=l"(r) : "f"(lo), "f"(hi));
    return r;
}
__device__ __forceinline__ void upk2(u64 v, float& lo, float& hi) {
    asm("mov.b64 {%0, %1}, %2;" : "=f"(lo), "=f"(hi) : "l"(v));
}

__global__ void init_tabs(const float* __restrict__ P) {
    int t = blockIdx.x * blockDim.x + threadIdx.x;
    if (t < ONUM * MM) {
        int k = t / MM, r = t % MM;
        int j = r >> 5, i = r & 31;
        g_CT[t] = cosf(6.283185307179586f * (float)k / (float)(i * MNUM + j + 2));
    } else if (t < ONUM * MM + MM) {
        int e = t - ONUM * MM;                    // e = j*32 + i
        g_PT[e] = P[(e & 31) * MNUM + (e >> 5)];
    }
}

// Fused, c-quartered: block = (a,b,cq). 4 blocks/SM for cross-block overlap.
#define FT 256                              // 8 warps
#define CQ 4
#define CRMAX 6                             // max c' rows (5 c-rows + halo)
#define H2F (CRMAX * DNUM * MNUM)           // 3840 floats
#define X2STR 33
#define X2F (CRMAX * DNUM * X2STR)          // 3960

__global__ __launch_bounds__(FT, 4) void fused(const float* __restrict__ h,
                                               const float* __restrict__ Mw,
                                               float* __restrict__ out) {
    __shared__ __align__(16) float sH2[H2F];   // A/B: H2[cl][d'][k]; C/D: WX[lc][j][d20]
    __shared__ __align__(16) float sX2[X2F];   // X2[cl][d'][j], stride 33
    __shared__ __align__(16) float sGab[MM];   // (P^T * Ca * Cb)[j][i]

    const int tid = threadIdx.x;
    const int blk = blockIdx.x;
    const int ab = blk >> 2, cq = blk & 3;
    const int a = ab / ONUM, b = ab % ONUM;
    const int c0 = cq * 5;
    const int crows = (cq < 3) ? 5 : 4;        // c rows this block outputs
    const int cr = crows + 1;                  // c' rows incl. halo
    const int w = tid >> 5, lane = tid & 31;

    // phase A0: Gab = PT .* Ca .* Cb (one float4 per thread)
    {
        float4 p  = ((const float4*)g_PT)[tid];
        float4 av = ((const float4*)(g_CT + a * MM))[tid];
        float4 bv = ((const float4*)(g_CT + b * MM))[tid];
        float4 o;
        o.x = p.x * av.x * bv.x;
        o.y = p.y * av.y * bv.y;
        o.z = p.z * av.z * bv.z;
        o.w = p.w * av.w * bv.w;
        ((float4*)sGab)[tid] = o;
    }

    // phase A: H2[cl][d'][k] = sum over {da,db} of h[a+da, b+db, c0+cl, d', k]
    // f4 base: (a*20+b)*3200 + c0*160; db:+3200, da:+64000 (in float4)
    {
        const float4* p00 = (const float4*)h + (a * DNUM + b) * 3200 + c0 * 160;
        float4* o4 = (float4*)sH2;
        const int tot = cr * 160;
        for (int e = tid; e < tot; e += FT) {
            float4 r0 = __ldg(p00 + e);
            float4 r1 = __ldg(p00 + e + 3200);
            float4 r2 = __ldg(p00 + e + 64000);
            float4 r3 = __ldg(p00 + e + 67200);
            float4 o;
            o.x = (r0.x + r1.x) + (r2.x + r3.x);
            o.y = (r0.y + r1.y) + (r2.y + r3.y);
            o.z = (r0.z + r1.z) + (r2.z + r3.z);
            o.w = (r0.w + r1.w) + (r2.w + r3.w);
            o4[e] = o;
        }
    }
    __syncthreads();

    // phase B: X2[cl][d'][j] = sum_k M[j,k] * H2[cl][d'][k]; lane = j, warp per pt
    {
        float Mr[MNUM];
        const float4* M4 = (const float4*)Mw + lane * 8;
#pragma unroll
        for (int v = 0; v < 8; ++v) {
            float4 m = __ldg(M4 + v);
            Mr[4*v+0] = m.x; Mr[4*v+1] = m.y; Mr[4*v+2] = m.z; Mr[4*v+3] = m.w;
        }
        const int npt = cr * DNUM;
        for (int pt = w; pt < npt; pt += FT / 32) {
            const float4* H4 = (const float4*)sH2 + pt * 8;
            float a0 = 0.f, a1 = 0.f, a2 = 0.f, a3 = 0.f;
#pragma unroll
            for (int v = 0; v < 8; ++v) {
                float4 hv = H4[v];                 // uniform LDS broadcast
                a0 = fmaf(Mr[4*v+0], hv.x, a0);
                a1 = fmaf(Mr[4*v+1], hv.y, a1);
                a2 = fmaf(Mr[4*v+2], hv.z, a2);
                a3 = fmaf(Mr[4*v+3], hv.w, a3);
            }
            sX2[pt * X2STR + lane] = (a0 + a1) + (a2 + a3);
        }
    }
    __syncthreads();

    // phase C: window over (c,d), transpose -> WX[lc][j][d(20, last=0)] over sH2
    {
        const int tot = crows * 160;
        for (int idx = tid; idx < tot; idx += FT) {
            const int lc = idx / 160, e = idx - lc * 160;
            const int f0 = e * 4;
            const int j0 = f0 / 20, d0 = f0 - (f0 / 20) * 20;  // 20%4==0
            const float* b0 = sX2 + (lc * DNUM + d0) * X2STR + j0;
            const float* b1 = b0 + DNUM * X2STR;
            float q[4];
#pragma unroll
            for (int t = 0; t < 4; ++t) {
                const int d = d0 + t;
                q[t] = (d < ONUM)
                     ? ((b0[t * X2STR] + b0[(t + 1) * X2STR])
                      + (b1[t * X2STR] + b1[(t + 1) * X2STR])) * 0.0625f
                     : 0.0f;
            }
            float4 v; v.x = q[0]; v.y = q[1]; v.z = q[2]; v.w = q[3];
            ((float4*)(sH2 + lc * 640))[e] = v;
        }
    }
    __syncthreads();

    // phase D: warp w = local row lc (< crows); lane = i; packed Chebyshev
    if (w < crows) {
        const int c = c0 + w;
        const float* Gl  = sGab + lane;
        const float* Cc  = g_CT + c * MM + lane;
        const float* C1  = g_CT + MM + lane;
        const ulonglong2* xs = (const ulonglong2*)(sH2 + w * 640);

        u64 acc[10];
#pragma unroll
        for (int k = 0; k < 10; ++k) acc[k] = 0ull;

#pragma unroll 2
        for (int j = 0; j < MNUM; ++j) {
            const int o = j * MNUM;
            const float tc = 2.0f * __ldg(C1 + o);
            const float u0 = Gl[o] * __ldg(Cc + o);
            const float csq = tc * tc;
            const u64 tc2  = pk2(csq - 2.0f, csq - 2.0f);
            const u64 ntc2 = pk2(2.0f - csq, 2.0f - csq);
            const float t1 = 0.5f * tc * u0;
            const float t2 = fmaf(tc, t1, -u0);
            const float t3 = fmaf(tc, t2, -t1);

            ulonglong2 xa = xs[j * 5 + 0];
            ulonglong2 xb = xs[j * 5 + 1];
            ulonglong2 xc = xs[j * 5 + 2];
            ulonglong2 xd = xs[j * 5 + 3];
            ulonglong2 xe = xs[j * 5 + 4];

            u64 s0 = pk2(u0, t1);
            u64 s1 = pk2(t2, t3);
            acc[0] = ffma2(xa.x, s0, acc[0]);
            acc[1] = ffma2(xa.y, s1, acc[1]);
            u64 s2 = ffma2(ntc2, s1, s0);
            acc[2] = ffma2(xb.x, s2, acc[2]);
            u64 s3 = ffma2(tc2, s2, s1);
            acc[3] = ffma2(xb.y, s3, acc[3]);
            s0 = ffma2(ntc2, s3, s2);
            acc[4] = ffma2(xc.x, s0, acc[4]);
            s1 = ffma2(tc2, s0, s3);
            acc[5] = ffma2(xc.y, s1, acc[5]);
            s2 = ffma2(ntc2, s1, s0);
            acc[6] = ffma2(xd.x, s2, acc[6]);
            s3 = ffma2(tc2, s2, s1);
            acc[7] = ffma2(xd.y, s3, acc[7]);
            s0 = ffma2(ntc2, s3, s2);
            acc[8] = ffma2(xe.x, s0, acc[8]);
            s1 = ffma2(tc2, s0, s3);
            acc[9] = ffma2(xe.y, s1, acc[9]);
        }

        float* op = out + (ab * ONUM + c) * ROWOUT + lane;
#pragma unroll
        for (int k = 0; k < 10; ++k) {
            float lo, hi;
            upk2(acc[k], lo, hi);
            const float s = (k & 2) ? -1.0f : 1.0f;
            op[(2 * k) * MNUM] = s * lo;
            if (2 * k + 1 < ONUM) op[(2 * k + 1) * MNUM] = s * hi;
        }
    }
}

extern "C" void kernel_launch(void* const* d_in, const int* in_sizes, int n_in,
                              void* d_out, int out_size) {
    const float* h  = (const float*)d_in[0];   // hypervol [20,20,20,20,32]
    const float* Mw = (const float*)d_in[1];   // M_w [32,32]
    const float* P  = (const float*)d_in[2];   // P  [32,32]
    float* out = (float*)d_out;                // [130321, 32]

    init_tabs<<<(ONUM * MM + MM + 511) / 512, 512>>>(P);
    fused<<<NAB * CQ, FT>>>(h, Mw, out);
}